// round 14
// baseline (speedup 1.0000x reference)
#include <cuda_runtime.h>
#include <cuda_bf16.h>
#include <math.h>
#include <stddef.h>
#include <stdint.h>

#define MAXN 131072
#define PI_F 3.14159265358979323846f

// ---------------- scratch (device globals: allocation-free) ----------------
__device__ float g_hin[(size_t)MAXN * 8];
__device__ __nv_bfloat16 g_hb0[(size_t)MAXN * 512];
__device__ __nv_bfloat16 g_hb1[(size_t)MAXN * 512];
__device__ float g_cs [(size_t)MAXN * 32];
__device__ __nv_bfloat16 g_w1b[512 * 512];
__device__ __nv_bfloat16 g_w2b[512 * 512];
__device__ __nv_bfloat16 g_w3b[512 * 512];
__device__ __nv_bfloat16 g_wct[32 * 512];
__device__ float g_bcp[32];
__device__ float g_F[66];          // K(l,m) * (sqrt2 if m>0), (m outer, l inner)

// ---------------- helpers ----------------
__device__ __forceinline__ float sigmoidf_(float x) {
    return 1.0f / (1.0f + expf(-x));
}
__device__ __forceinline__ float softplusf_(float x) {
    return fmaxf(x, 0.0f) + log1pf(expf(-fabsf(x)));
}
__device__ __forceinline__ void cpa16(uint32_t s, const void* g) {
    asm volatile("cp.async.cg.shared.global [%0], [%1], 16;\n" :: "r"(s), "l"(g));
}
__device__ __forceinline__ void cpa_commit() {
    asm volatile("cp.async.commit_group;\n" ::: "memory");
}
template<int NN>
__device__ __forceinline__ void cpa_wait() {
    asm volatile("cp.async.wait_group %0;\n" :: "n"(NN) : "memory");
}
__device__ __forceinline__ void mma_bf16(float* d, const uint32_t* a, const uint32_t* b) {
    asm volatile(
        "mma.sync.aligned.m16n8k16.row.col.f32.bf16.bf16.f32 "
        "{%0,%1,%2,%3}, {%4,%5,%6,%7}, {%8,%9}, {%0,%1,%2,%3};\n"
        : "+f"(d[0]), "+f"(d[1]), "+f"(d[2]), "+f"(d[3])
        : "r"(a[0]), "r"(a[1]), "r"(a[2]), "r"(a[3]), "r"(b[0]), "r"(b[1]));
}
__device__ __forceinline__ void ldm_x4(uint32_t* r, uint32_t addr) {
    asm volatile("ldmatrix.sync.aligned.m8n8.x4.shared.b16 {%0,%1,%2,%3}, [%4];"
        : "=r"(r[0]), "=r"(r[1]), "=r"(r[2]), "=r"(r[3]) : "r"(addr));
}

// ---------------- SH constant table (double precision, device-side) --------
__global__ void shconst_kernel(float* __restrict__ F)
{
    if (threadIdx.x == 0 && blockIdx.x == 0) {
        int idx = 0;
        for (int m = 0; m <= 10; ++m) {
            for (int l = m; l <= 10; ++l) {
                double num = 1.0;
                for (int t = l - m + 1; t <= l + m; ++t) num *= (double)t;
                double kc = sqrt((double)(2 * l + 1) /
                                 (4.0 * 3.14159265358979323846 * num));
                if (m > 0) kc *= 1.4142135623730951;
                F[idx++] = (float)kc;
            }
        }
    }
}

// ---------------- kernel A: SH basis + pointwise prep ----------------
__global__ __launch_bounds__(128)
void point_kernel(const float* __restrict__ normals,
                  const float* __restrict__ view_dirs,
                  const float* __restrict__ feature,
                  const float* __restrict__ ref_SH,
                  const float* __restrict__ F,
                  float* __restrict__ out,
                  float* __restrict__ hin,
                  int N)
{
    int n = blockIdx.x * blockDim.x + threadIdx.x;
    if (n >= N) return;

    const float LAM[11] = {
        3.1415926535897927f, 2.0943951023931957f, 0.7853981633974483f, 0.0f,
        -0.13089969389957473f, 0.0f, 0.04908738521234052f, 0.0f,
        -0.024543692606170262f, 0.0f, 0.014317154020265985f };

    float nx = normals[n*3+0], ny = normals[n*3+1], nz = normals[n*3+2];
    float vx = view_dirs[n*3+0], vy = view_dirs[n*3+1], vz = view_dirs[n*3+2];

    float dt = nx*vx + ny*vy + nz*vz;
    float wx = 2.0f*nx*dt - vx;
    float wy = 2.0f*ny*dt - vy;
    float wz = 2.0f*nz*dt - vz;

    float rN = sqrtf(nx*nx + ny*ny + nz*nz);
    float iN = 1.0f / fmaxf(rN, 1e-12f);
    float xN = nx*iN, yN = ny*iN, zN = nz*iN;
    float rW = sqrtf(wx*wx + wy*wy + wz*wz);
    float iW = 1.0f / fmaxf(rW, 1e-12f);
    float xW = wx*iW, yW = wy*iW, zW = wz*iW;

    float f0 = feature[(size_t)n*16 + 0];
    float rough = softplusf_(f0);

    float fNl[11], fWl[11];
    {
        float rpN = 1.0f, rpW = 1.0f;
        #pragma unroll
        for (int l = 0; l <= 10; ++l) {
            fNl[l] = LAM[l] * rpN;
            fWl[l] = expf(-(0.5f * (float)(l*(l+1))) * rough) * rpW;
            rpN *= rN; rpW *= rW;
        }
    }

    const float* __restrict__ refp = ref_SH + (size_t)n * 363;

    float aI0=0.f, aI1=0.f, aI2=0.f;
    float aL0=0.f, aL1=0.f, aL2=0.f;

    float cN = 1.0f, sN = 0.0f, cW = 1.0f, sW = 0.0f;

    int fidx = 0;
    #pragma unroll
    for (int m = 0; m <= 10; ++m) {
        if (m > 0) {
            float tN = xN*cN - yN*sN; sN = xN*sN + yN*cN; cN = tN;
            float tW = xW*cW - yW*sW; sW = xW*sW + yW*cW; cW = tW;
        }
        float dfm = 1.0f;
        #pragma unroll
        for (int t = 2*m - 1; t > 0; t -= 2) dfm *= (float)t;

        float QN1 = 0.f, QN2 = 0.f, QW1 = 0.f, QW2 = 0.f;
        #pragma unroll
        for (int l = m; l <= 10; ++l) {
            float QN, QW;
            if (l == m)          { QN = dfm; QW = dfm; }
            else if (l == m + 1) { float c0 = (float)(2*m + 1);
                                   QN = c0 * zN * QN1; QW = c0 * zW * QW1; }
            else                 { float c1 = (float)(2*l - 1);
                                   float c2 = (float)(l + m - 1);
                                   float c3 = 1.0f / (float)(l - m);
                                   QN = (c1 * zN * QN1 - c2 * QN2) * c3;
                                   QW = (c1 * zW * QW1 - c2 * QW2) * c3; }
            QN2 = QN1; QN1 = QN;
            QW2 = QW1; QW1 = QW;

            float kc = __ldg(&F[fidx]);
            ++fidx;

            int bi = l*l + l;
            if (m == 0) {
                float wI = fNl[l] * kc * QN;
                float wL = fWl[l] * kc * QW;
                const float* rp = refp + (size_t)bi * 3;
                float r0 = __ldcs(rp + 0), r1 = __ldcs(rp + 1), r2 = __ldcs(rp + 2);
                aI0 += wI*r0; aI1 += wI*r1; aI2 += wI*r2;
                aL0 += wL*r0; aL1 += wL*r1; aL2 += wL*r2;
            } else {
                float kQN = kc * QN, kQW = kc * QW;
                float wIc = fNl[l]*kQN*cN, wIs = fNl[l]*kQN*sN;
                float wLc = fWl[l]*kQW*cW, wLs = fWl[l]*kQW*sW;
                const float* rc = refp + (size_t)(bi + m) * 3;
                const float* rs = refp + (size_t)(bi - m) * 3;
                float c0 = __ldcs(rc + 0), c1 = __ldcs(rc + 1), c2 = __ldcs(rc + 2);
                float s0 = __ldcs(rs + 0), s1 = __ldcs(rs + 1), s2 = __ldcs(rs + 2);
                aI0 += wIc*c0 + wIs*s0;
                aI1 += wIc*c1 + wIs*s1;
                aI2 += wIc*c2 + wIs*s2;
                aL0 += wLc*c0 + wLs*s0;
                aL1 += wLc*c1 + wLs*s1;
                aL2 += wLc*c2 + wLs*s2;
            }
        }
    }

    float ir0 = fmaxf(aI0, 0.f), ir1 = fmaxf(aI1, 0.f), ir2 = fmaxf(aI2, 0.f);
    float li0 = fmaxf(aL0, 0.f), li1 = fmaxf(aL1, 0.f), li2 = fmaxf(aL2, 0.f);

    float al0 = sigmoidf_(feature[(size_t)n*16 + 10]);
    float al1 = sigmoidf_(feature[(size_t)n*16 + 11]);
    float al2 = sigmoidf_(feature[(size_t)n*16 + 12]);

    float df0 = al0*ir0, df1 = al1*ir1, df2 = al2*ir2;

    size_t N3 = 3 * (size_t)N;
    size_t p3 = (size_t)n * 3;
    out[N3   + p3 + 0] = al0; out[N3   + p3 + 1] = al1; out[N3   + p3 + 2] = al2;
    out[2*N3 + p3 + 0] = df0; out[2*N3 + p3 + 1] = df1; out[2*N3 + p3 + 2] = df2;
    out[4*N3 + p3 + 0] = li0; out[4*N3 + p3 + 1] = li1; out[4*N3 + p3 + 2] = li2;
    out[5*N3 + p3 + 0] = ir0; out[5*N3 + p3 + 1] = ir1; out[5*N3 + p3 + 2] = ir2;

    float* h = hin + (size_t)n * 8;
    h[0] = dt; h[1] = vx; h[2] = vy; h[3] = vz;
    h[4] = nx; h[5] = ny; h[6] = nz; h[7] = rough;
}

// ---------------- layer0: [N,8]@[8,512] -> relu -> bf16 (broadcast smem) ----
__global__ __launch_bounds__(256)
void layer0_kernel(const float* __restrict__ hin,
                   const float* __restrict__ w0,
                   const float* __restrict__ b0,
                   __nv_bfloat16* __restrict__ C)
{
    __shared__ float w0s[8 * 512];
    __shared__ float b0s[512];
    __shared__ float ins[64 * 8];

    const int tid = threadIdx.x;
    #pragma unroll
    for (int i = tid; i < 4096; i += 256) w0s[i] = w0[i];
    for (int i = tid; i < 512; i += 256) b0s[i] = b0[i];
    const int pbase = blockIdx.x * 64;
    for (int i = tid; i < 512; i += 256) ins[i] = hin[(size_t)pbase * 8 + i];
    __syncthreads();

    const int p     = tid & 63;
    const int chunk = tid >> 6;

    float in[8];
    #pragma unroll
    for (int k = 0; k < 8; ++k) in[k] = ins[p * 8 + k];

    __nv_bfloat16* Crow = C + ((size_t)(pbase + p)) * 512 + chunk * 128;
    const int cb = chunk * 128;

    #pragma unroll 2
    for (int j0 = 0; j0 < 128; j0 += 8) {
        float o[8];
        #pragma unroll
        for (int q = 0; q < 8; ++q) o[q] = b0s[cb + j0 + q];
        #pragma unroll
        for (int k = 0; k < 8; ++k) {
            float4 lo = *(const float4*)&w0s[k * 512 + cb + j0];
            float4 hi = *(const float4*)&w0s[k * 512 + cb + j0 + 4];
            o[0] += in[k] * lo.x; o[1] += in[k] * lo.y;
            o[2] += in[k] * lo.z; o[3] += in[k] * lo.w;
            o[4] += in[k] * hi.x; o[5] += in[k] * hi.y;
            o[6] += in[k] * hi.z; o[7] += in[k] * hi.w;
        }
        __nv_bfloat162 v[4];
        #pragma unroll
        for (int q = 0; q < 4; ++q)
            v[q] = __floats2bfloat162_rn(fmaxf(o[2*q], 0.0f), fmaxf(o[2*q+1], 0.0f));
        *(uint4*)(Crow + j0) = *(uint4*)v;
    }
}

// ---------------- bf16 tensor-core GEMM, K=512, ldmatrix fragments ---------
#define W_STRIDE 20
#define ROWB (W_STRIDE * 4)

__global__ __launch_bounds__(256, 2)
void bf16_gemm(const __nv_bfloat16* __restrict__ A,
               const __nv_bfloat16* __restrict__ Bt,
               const float* __restrict__ bias,
               __nv_bfloat16* __restrict__ C)
{
    __shared__ uint32_t As[2][128 * W_STRIDE];
    __shared__ uint32_t Bs[2][128 * W_STRIDE];

    const int tid  = threadIdx.x;
    const int bN   = blockIdx.x;
    const int bM   = blockIdx.y;
    const int lane = tid & 31;
    const int warp = tid >> 5;
    const int wM = warp >> 2;
    const int wN = warp & 3;
    const int g  = lane >> 2;
    const int tg = lane & 3;

    const int ldrow = tid >> 2;
    const int ldch  = tid & 3;

    uint32_t sA0 = (uint32_t)__cvta_generic_to_shared(&As[0][0]);
    uint32_t sA1 = (uint32_t)__cvta_generic_to_shared(&As[1][0]);
    uint32_t sB0 = (uint32_t)__cvta_generic_to_shared(&Bs[0][0]);
    uint32_t sB1 = (uint32_t)__cvta_generic_to_shared(&Bs[1][0]);

    const uint32_t offA = (uint32_t)((lane & 15) * ROWB + ((lane >> 4) * 16))
                        + (uint32_t)(wM * 64 * ROWB);
    const uint32_t offB = (uint32_t)(((lane & 7) + ((lane >> 4) << 3)) * ROWB
                        + (((lane >> 3) & 1) * 16))
                        + (uint32_t)(wN * 32 * ROWB);

    const __nv_bfloat16* Agb = A  + ((size_t)bM * 128 + ldrow) * 512 + ldch * 8;
    const __nv_bfloat16* Bgb = Bt + ((size_t)bN * 128 + ldrow) * 512 + ldch * 8;

    float acc[4][4][4];
    #pragma unroll
    for (int i = 0; i < 4; ++i)
        #pragma unroll
        for (int j = 0; j < 4; ++j)
            #pragma unroll
            for (int q = 0; q < 4; ++q) acc[i][j][q] = 0.0f;

    auto issue = [&](int kt, uint32_t sA, uint32_t sB) {
        const __nv_bfloat16* Ag = Agb + kt * 32;
        uint32_t da = sA + ((ldrow * W_STRIDE + ldch * 4) << 2);
        cpa16(da, Ag);
        cpa16(da + ((64 * W_STRIDE) << 2), Ag + (size_t)64 * 512);
        const __nv_bfloat16* Bg = Bgb + kt * 32;
        uint32_t db = sB + ((ldrow * W_STRIDE + ldch * 4) << 2);
        cpa16(db, Bg);
        cpa16(db + ((64 * W_STRIDE) << 2), Bg + (size_t)64 * 512);
    };

    issue(0, sA0, sB0);
    cpa_commit();

    #pragma unroll 1
    for (int t = 0; t < 16; ++t) {
        int cur = t & 1;
        if (t < 15) {
            issue(t + 1, cur ? sA0 : sA1, cur ? sB0 : sB1);
            cpa_commit();
            cpa_wait<1>();
        } else {
            cpa_wait<0>();
        }
        __syncthreads();

        uint32_t aBase = (cur ? sA1 : sA0) + offA;
        uint32_t bBase = (cur ? sB1 : sB0) + offB;

        #pragma unroll
        for (int ks = 0; ks < 2; ++ks) {
            uint32_t a[4][4], bp[2][4];
            #pragma unroll
            for (int mf = 0; mf < 4; ++mf)
                ldm_x4(a[mf], aBase + mf * (16 * ROWB) + ks * 32);
            #pragma unroll
            for (int p = 0; p < 2; ++p)
                ldm_x4(bp[p], bBase + p * (16 * ROWB) + ks * 32);
            #pragma unroll
            for (int mf = 0; mf < 4; ++mf)
                #pragma unroll
                for (int nf = 0; nf < 4; ++nf)
                    mma_bf16(acc[mf][nf], a[mf], &bp[nf >> 1][(nf & 1) * 2]);
        }
        __syncthreads();
    }

    #pragma unroll
    for (int mf = 0; mf < 4; ++mf) {
        int row0 = bM * 128 + wM * 64 + mf * 16 + g;
        #pragma unroll
        for (int nf = 0; nf < 4; ++nf) {
            int col = bN * 128 + wN * 32 + nf * 8 + tg * 2;
            float b0 = bias[col], b1 = bias[col + 1];
            float v00 = fmaxf(acc[mf][nf][0] + b0, 0.0f);
            float v01 = fmaxf(acc[mf][nf][1] + b1, 0.0f);
            float v10 = fmaxf(acc[mf][nf][2] + b0, 0.0f);
            float v11 = fmaxf(acc[mf][nf][3] + b1, 0.0f);
            *(__nv_bfloat162*)(C + (size_t)row0 * 512 + col) =
                __floats2bfloat162_rn(v00, v01);
            *(__nv_bfloat162*)(C + (size_t)(row0 + 8) * 512 + col) =
                __floats2bfloat162_rn(v10, v11);
        }
    }
}

// ---------------- head: [N,512] @ wct^T(32x512) -> fp32 cs[N][32] ----------
__global__ __launch_bounds__(256, 2)
void head_gemm(const __nv_bfloat16* __restrict__ A,
               const __nv_bfloat16* __restrict__ Bt,   // [32][512]
               const float* __restrict__ bias,          // [32]
               float* __restrict__ cs)                  // [N][32]
{
    __shared__ uint32_t As[2][128 * W_STRIDE];
    __shared__ uint32_t Bs[2][32 * W_STRIDE];

    const int tid  = threadIdx.x;
    const int bM   = blockIdx.y;
    const int lane = tid & 31;
    const int warp = tid >> 5;       // 0..7, each owns 16 rows x 32 cols
    const int g  = lane >> 2;
    const int tg = lane & 3;

    const int ldrow = tid >> 2;
    const int ldch  = tid & 3;

    uint32_t sA0 = (uint32_t)__cvta_generic_to_shared(&As[0][0]);
    uint32_t sA1 = (uint32_t)__cvta_generic_to_shared(&As[1][0]);
    uint32_t sB0 = (uint32_t)__cvta_generic_to_shared(&Bs[0][0]);
    uint32_t sB1 = (uint32_t)__cvta_generic_to_shared(&Bs[1][0]);

    const uint32_t offA = (uint32_t)((lane & 15) * ROWB + ((lane >> 4) * 16))
                        + (uint32_t)(warp * 16 * ROWB);
    const uint32_t offB = (uint32_t)(((lane & 7) + ((lane >> 4) << 3)) * ROWB
                        + (((lane >> 3) & 1) * 16));

    const __nv_bfloat16* Agb = A  + ((size_t)bM * 128 + ldrow) * 512 + ldch * 8;
    const __nv_bfloat16* Bgb = Bt + ((size_t)(ldrow & 31)) * 512 + ldch * 8;

    float acc[4][4];
    #pragma unroll
    for (int j = 0; j < 4; ++j)
        #pragma unroll
        for (int q = 0; q < 4; ++q) acc[j][q] = 0.0f;

    auto issue = [&](int kt, uint32_t sA, uint32_t sB) {
        const __nv_bfloat16* Ag = Agb + kt * 32;
        uint32_t da = sA + ((ldrow * W_STRIDE + ldch * 4) << 2);
        cpa16(da, Ag);
        cpa16(da + ((64 * W_STRIDE) << 2), Ag + (size_t)64 * 512);
        if (tid < 128) {
            const __nv_bfloat16* Bg = Bgb + kt * 32;
            uint32_t db = sB + ((ldrow * W_STRIDE + ldch * 4) << 2);
            cpa16(db, Bg);
        }
    };

    issue(0, sA0, sB0);
    cpa_commit();

    #pragma unroll 1
    for (int t = 0; t < 16; ++t) {
        int cur = t & 1;
        if (t < 15) {
            issue(t + 1, cur ? sA0 : sA1, cur ? sB0 : sB1);
            cpa_commit();
            cpa_wait<1>();
        } else {
            cpa_wait<0>();
        }
        __syncthreads();

        uint32_t aBase = (cur ? sA1 : sA0) + offA;
        uint32_t bBase = (cur ? sB1 : sB0) + offB;

        #pragma unroll
        for (int ks = 0; ks < 2; ++ks) {
            uint32_t a[4], bp[2][4];
            ldm_x4(a, aBase + ks * 32);
            #pragma unroll
            for (int p = 0; p < 2; ++p)
                ldm_x4(bp[p], bBase + p * (16 * ROWB) + ks * 32);
            #pragma unroll
            for (int nf = 0; nf < 4; ++nf)
                mma_bf16(acc[nf], a, &bp[nf >> 1][(nf & 1) * 2]);
        }
        __syncthreads();
    }

    const int row0 = bM * 128 + warp * 16 + g;
    #pragma unroll
    for (int nf = 0; nf < 4; ++nf) {
        int col = nf * 8 + tg * 2;
        float b0 = bias[col], b1 = bias[col + 1];
        *(float2*)(cs + (size_t)row0 * 32 + col) =
            make_float2(acc[nf][0] + b0, acc[nf][1] + b1);
        *(float2*)(cs + (size_t)(row0 + 8) * 32 + col) =
            make_float2(acc[nf][2] + b0, acc[nf][3] + b1);
    }
}

// ---------------- weight transpose + bf16 convert ----------------
__global__ void wt_kernel(const float* __restrict__ w1,
                          const float* __restrict__ w2,
                          const float* __restrict__ w3,
                          __nv_bfloat16* __restrict__ o1,
                          __nv_bfloat16* __restrict__ o2,
                          __nv_bfloat16* __restrict__ o3)
{
    __shared__ float tile[32][33];
    const float* src = (blockIdx.z == 0) ? w1 : (blockIdx.z == 1) ? w2 : w3;
    __nv_bfloat16* dst = (blockIdx.z == 0) ? o1 : (blockIdx.z == 1) ? o2 : o3;

    int bx = blockIdx.x * 32;
    int by = blockIdx.y * 32;
    int tx = threadIdx.x, ty = threadIdx.y;

    #pragma unroll
    for (int j = 0; j < 32; j += 8)
        tile[ty + j][tx] = src[(size_t)(bx + ty + j) * 512 + by + tx];
    __syncthreads();
    #pragma unroll
    for (int j = 0; j < 32; j += 8)
        dst[(size_t)(by + ty + j) * 512 + bx + tx] =
            __float2bfloat16_rn(tile[tx][ty + j]);
}

// ---------------- head weight prep: wc[512][27] -> wct[32][512] bf16 -------
__global__ void headprep_kernel(const float* __restrict__ wc,
                                const float* __restrict__ bc,
                                __nv_bfloat16* __restrict__ wct,
                                float* __restrict__ bcp)
{
    int i = blockIdx.x * blockDim.x + threadIdx.x;
    if (i < 32 * 512) {
        int n = i / 512, k = i % 512;
        wct[i] = __float2bfloat16_rn((n < 27) ? wc[(size_t)k * 27 + n] : 0.0f);
    }
    if (i < 32) bcp[i] = (i < 27) ? bc[i] : 0.0f;
}

// ---------------- kernel C: gate + specular + raw_rgb ----------------
__global__ void final_kernel(const float* __restrict__ feature,
                             const float* __restrict__ cs,   // [N][32]
                             float* __restrict__ out,
                             int N)
{
    int n = blockIdx.x * blockDim.x + threadIdx.x;
    if (n >= N) return;

    const float* f = feature + (size_t)n * 16;
    const float* c = cs + (size_t)n * 32;

    float g0 = 0.f, g1 = 0.f, g2 = 0.f;
    #pragma unroll
    for (int j = 0; j < 9; ++j) {
        float coe = f[1 + j];
        g0 += c[j]      * coe;
        g1 += c[9 + j]  * coe;
        g2 += c[18 + j] * coe;
    }
    g0 = sigmoidf_(g0); g1 = sigmoidf_(g1); g2 = sigmoidf_(g2);

    float sp0 = sigmoidf_(f[13]);
    float sp1 = sigmoidf_(f[14]);
    float sp2 = sigmoidf_(f[15]);

    size_t N3 = 3 * (size_t)N;
    size_t p3 = (size_t)n * 3;

    float li0 = out[4*N3 + p3 + 0];
    float li1 = out[4*N3 + p3 + 1];
    float li2 = out[4*N3 + p3 + 2];

    float s0 = sp0 * li0 * g0;
    float s1 = sp1 * li1 * g1;
    float s2 = sp2 * li2 * g2;

    out[3*N3 + p3 + 0] = s0;
    out[3*N3 + p3 + 1] = s1;
    out[3*N3 + p3 + 2] = s2;
    out[p3 + 0] = out[2*N3 + p3 + 0] + s0;
    out[p3 + 1] = out[2*N3 + p3 + 1] + s1;
    out[p3 + 2] = out[2*N3 + p3 + 2] + s2;
}

// ---------------- launch ----------------
extern "C" void kernel_launch(void* const* d_in, const int* in_sizes, int n_in,
                              void* d_out, int out_size)
{
    const float* normals   = (const float*)d_in[0];
    const float* view_dirs = (const float*)d_in[1];
    const float* feature   = (const float*)d_in[2];
    const float* ref_SH    = (const float*)d_in[3];
    const float* w0 = (const float*)d_in[4];
    const float* b0 = (const float*)d_in[5];
    const float* w1 = (const float*)d_in[6];
    const float* b1 = (const float*)d_in[7];
    const float* w2 = (const float*)d_in[8];
    const float* b2 = (const float*)d_in[9];
    const float* w3 = (const float*)d_in[10];
    const float* b3 = (const float*)d_in[11];
    const float* wc = (const float*)d_in[12];
    const float* bc = (const float*)d_in[13];

    int N = in_sizes[0] / 3;
    float* out = (float*)d_out;

    float *hin, *cs, *bcp, *Ftab;
    __nv_bfloat16 *hb0, *hb1, *w1b, *w2b, *w3b, *wct;
    cudaGetSymbolAddress((void**)&hin, g_hin);
    cudaGetSymbolAddress((void**)&hb0, g_hb0);
    cudaGetSymbolAddress((void**)&hb1, g_hb1);
    cudaGetSymbolAddress((void**)&cs,  g_cs);
    cudaGetSymbolAddress((void**)&w1b, g_w1b);
    cudaGetSymbolAddress((void**)&w2b, g_w2b);
    cudaGetSymbolAddress((void**)&w3b, g_w3b);
    cudaGetSymbolAddress((void**)&wct, g_wct);
    cudaGetSymbolAddress((void**)&bcp, g_bcp);
    cudaGetSymbolAddress((void**)&Ftab, g_F);

    shconst_kernel<<<1, 32>>>(Ftab);
    point_kernel<<<(N + 127) / 128, 128>>>(normals, view_dirs, feature, ref_SH,
                                           Ftab, out, hin, N);
    wt_kernel<<<dim3(16, 16, 3), dim3(32, 8)>>>(w1, w2, w3, w1b, w2b, w3b);
    headprep_kernel<<<(32 * 512 + 255) / 256, 256>>>(wc, bc, wct, bcp);

    int mtiles = N / 128;
    layer0_kernel<<<N / 64, 256>>>(hin, w0, b0, hb0);
    bf16_gemm<<<dim3(4, mtiles), 256>>>(hb0, w1b, b1, hb1);
    bf16_gemm<<<dim3(4, mtiles), 256>>>(hb1, w2b, b2, hb0);
    bf16_gemm<<<dim3(4, mtiles), 256>>>(hb0, w3b, b3, hb1);
    head_gemm<<<dim3(1, mtiles), 256>>>(hb1, wct, bcp, cs);

    final_kernel<<<(N + 255) / 256, 256>>>(feature, cs, out, N);
}

// round 15
// speedup vs baseline: 1.1399x; 1.1399x over previous
#include <cuda_runtime.h>
#include <cuda_bf16.h>
#include <math.h>
#include <stddef.h>
#include <stdint.h>

#define MAXN 131072
#define PI_F 3.14159265358979323846f

// ---------------- scratch (device globals: allocation-free) ----------------
__device__ float g_hin[(size_t)MAXN * 8];
__device__ __nv_bfloat16 g_hb0[(size_t)MAXN * 512];
__device__ __nv_bfloat16 g_hb1[(size_t)MAXN * 512];
__device__ float g_cs [(size_t)MAXN * 32];
__device__ __nv_bfloat16 g_w1b[512 * 512];
__device__ __nv_bfloat16 g_w2b[512 * 512];
__device__ __nv_bfloat16 g_w3b[512 * 512];
__device__ __nv_bfloat16 g_wct[32 * 512];
__device__ float g_bcp[32];

// ---------------- helpers ----------------
__device__ __forceinline__ float sigmoidf_(float x) {
    return 1.0f / (1.0f + expf(-x));
}
__device__ __forceinline__ float softplusf_(float x) {
    return fmaxf(x, 0.0f) + log1pf(expf(-fabsf(x)));
}
__device__ __forceinline__ void cpa16(uint32_t s, const void* g) {
    asm volatile("cp.async.cg.shared.global [%0], [%1], 16;\n" :: "r"(s), "l"(g));
}
__device__ __forceinline__ void cpa_commit() {
    asm volatile("cp.async.commit_group;\n" ::: "memory");
}
template<int NN>
__device__ __forceinline__ void cpa_wait() {
    asm volatile("cp.async.wait_group %0;\n" :: "n"(NN) : "memory");
}
__device__ __forceinline__ void mma_bf16(float* d, const uint32_t* a, const uint32_t* b) {
    asm volatile(
        "mma.sync.aligned.m16n8k16.row.col.f32.bf16.bf16.f32 "
        "{%0,%1,%2,%3}, {%4,%5,%6,%7}, {%8,%9}, {%0,%1,%2,%3};\n"
        : "+f"(d[0]), "+f"(d[1]), "+f"(d[2]), "+f"(d[3])
        : "r"(a[0]), "r"(a[1]), "r"(a[2]), "r"(a[3]), "r"(b[0]), "r"(b[1]));
}
__device__ __forceinline__ void ldm_x4(uint32_t* r, uint32_t addr) {
    asm volatile("ldmatrix.sync.aligned.m8n8.x4.shared.b16 {%0,%1,%2,%3}, [%4];"
        : "=r"(r[0]), "=r"(r[1]), "=r"(r[2]), "=r"(r[3]) : "r"(addr));
}

// ---------------- kernel A: SH basis + pointwise prep ----------------
// (round-11 version: inline constants constant-folded by nvcc, plain loads)
__global__ __launch_bounds__(128)
void point_kernel(const float* __restrict__ normals,
                  const float* __restrict__ view_dirs,
                  const float* __restrict__ feature,
                  const float* __restrict__ ref_SH,
                  float* __restrict__ out,
                  float* __restrict__ hin,
                  int N)
{
    int n = blockIdx.x * blockDim.x + threadIdx.x;
    if (n >= N) return;

    const float LAM[11] = {
        3.1415926535897927f, 2.0943951023931957f, 0.7853981633974483f, 0.0f,
        -0.13089969389957473f, 0.0f, 0.04908738521234052f, 0.0f,
        -0.024543692606170262f, 0.0f, 0.014317154020265985f };

    float nx = normals[n*3+0], ny = normals[n*3+1], nz = normals[n*3+2];
    float vx = view_dirs[n*3+0], vy = view_dirs[n*3+1], vz = view_dirs[n*3+2];

    float dt = nx*vx + ny*vy + nz*vz;
    float wx = 2.0f*nx*dt - vx;
    float wy = 2.0f*ny*dt - vy;
    float wz = 2.0f*nz*dt - vz;

    float rN = sqrtf(nx*nx + ny*ny + nz*nz);
    float iN = 1.0f / fmaxf(rN, 1e-12f);
    float xN = nx*iN, yN = ny*iN, zN = nz*iN;
    float rW = sqrtf(wx*wx + wy*wy + wz*wz);
    float iW = 1.0f / fmaxf(rW, 1e-12f);
    float xW = wx*iW, yW = wy*iW, zW = wz*iW;

    float f0 = feature[(size_t)n*16 + 0];
    float rough = softplusf_(f0);

    float fNl[11], fWl[11];
    {
        float rpN = 1.0f, rpW = 1.0f;
        #pragma unroll
        for (int l = 0; l <= 10; ++l) {
            fNl[l] = LAM[l] * rpN;
            fWl[l] = expf(-(0.5f * (float)(l*(l+1))) * rough) * rpW;
            rpN *= rN; rpW *= rW;
        }
    }

    const float* __restrict__ refp = ref_SH + (size_t)n * 363;

    float aI0=0.f, aI1=0.f, aI2=0.f;
    float aL0=0.f, aL1=0.f, aL2=0.f;

    float cN = 1.0f, sN = 0.0f, cW = 1.0f, sW = 0.0f;

    #pragma unroll
    for (int m = 0; m <= 10; ++m) {
        if (m > 0) {
            float tN = xN*cN - yN*sN; sN = xN*sN + yN*cN; cN = tN;
            float tW = xW*cW - yW*sW; sW = xW*sW + yW*cW; cW = tW;
        }
        float dfm = 1.0f;
        #pragma unroll
        for (int t = 2*m - 1; t > 0; t -= 2) dfm *= (float)t;

        float QN1 = 0.f, QN2 = 0.f, QW1 = 0.f, QW2 = 0.f;
        #pragma unroll
        for (int l = m; l <= 10; ++l) {
            float QN, QW;
            if (l == m)          { QN = dfm; QW = dfm; }
            else if (l == m + 1) { float c0 = (float)(2*m + 1);
                                   QN = c0 * zN * QN1; QW = c0 * zW * QW1; }
            else                 { float c1 = (float)(2*l - 1);
                                   float c2 = (float)(l + m - 1);
                                   float c3 = 1.0f / (float)(l - m);
                                   QN = (c1 * zN * QN1 - c2 * QN2) * c3;
                                   QW = (c1 * zW * QW1 - c2 * QW2) * c3; }
            QN2 = QN1; QN1 = QN;
            QW2 = QW1; QW1 = QW;

            float num = 1.0f;
            #pragma unroll
            for (int t = l - m + 1; t <= l + m; ++t) num *= (float)t;
            float kc = sqrtf((float)(2*l + 1) / (4.0f * PI_F * num));
            if (m > 0) kc *= 1.4142135623730951f;

            int bi = l*l + l;
            if (m == 0) {
                float wI = fNl[l] * kc * QN;
                float wL = fWl[l] * kc * QW;
                const float* rp = refp + (size_t)bi * 3;
                float r0 = rp[0], r1 = rp[1], r2 = rp[2];
                aI0 += wI*r0; aI1 += wI*r1; aI2 += wI*r2;
                aL0 += wL*r0; aL1 += wL*r1; aL2 += wL*r2;
            } else {
                float kQN = kc * QN, kQW = kc * QW;
                float wIc = fNl[l]*kQN*cN, wIs = fNl[l]*kQN*sN;
                float wLc = fWl[l]*kQW*cW, wLs = fWl[l]*kQW*sW;
                const float* rc = refp + (size_t)(bi + m) * 3;
                const float* rs = refp + (size_t)(bi - m) * 3;
                float c0 = rc[0], c1 = rc[1], c2 = rc[2];
                float s0 = rs[0], s1 = rs[1], s2 = rs[2];
                aI0 += wIc*c0 + wIs*s0;
                aI1 += wIc*c1 + wIs*s1;
                aI2 += wIc*c2 + wIs*s2;
                aL0 += wLc*c0 + wLs*s0;
                aL1 += wLc*c1 + wLs*s1;
                aL2 += wLc*c2 + wLs*s2;
            }
        }
    }

    float ir0 = fmaxf(aI0, 0.f), ir1 = fmaxf(aI1, 0.f), ir2 = fmaxf(aI2, 0.f);
    float li0 = fmaxf(aL0, 0.f), li1 = fmaxf(aL1, 0.f), li2 = fmaxf(aL2, 0.f);

    float al0 = sigmoidf_(feature[(size_t)n*16 + 10]);
    float al1 = sigmoidf_(feature[(size_t)n*16 + 11]);
    float al2 = sigmoidf_(feature[(size_t)n*16 + 12]);

    float df0 = al0*ir0, df1 = al1*ir1, df2 = al2*ir2;

    size_t N3 = 3 * (size_t)N;
    size_t p3 = (size_t)n * 3;
    out[N3   + p3 + 0] = al0; out[N3   + p3 + 1] = al1; out[N3   + p3 + 2] = al2;
    out[2*N3 + p3 + 0] = df0; out[2*N3 + p3 + 1] = df1; out[2*N3 + p3 + 2] = df2;
    out[4*N3 + p3 + 0] = li0; out[4*N3 + p3 + 1] = li1; out[4*N3 + p3 + 2] = li2;
    out[5*N3 + p3 + 0] = ir0; out[5*N3 + p3 + 1] = ir1; out[5*N3 + p3 + 2] = ir2;

    float* h = hin + (size_t)n * 8;
    h[0] = dt; h[1] = vx; h[2] = vy; h[3] = vz;
    h[4] = nx; h[5] = ny; h[6] = nz; h[7] = rough;
}

// ---------------- layer0: [N,8]@[8,512] -> relu -> bf16 (broadcast smem) ----
__global__ __launch_bounds__(256)
void layer0_kernel(const float* __restrict__ hin,
                   const float* __restrict__ w0,
                   const float* __restrict__ b0,
                   __nv_bfloat16* __restrict__ C)
{
    __shared__ float w0s[8 * 512];
    __shared__ float b0s[512];
    __shared__ float ins[64 * 8];

    const int tid = threadIdx.x;
    #pragma unroll
    for (int i = tid; i < 4096; i += 256) w0s[i] = w0[i];
    for (int i = tid; i < 512; i += 256) b0s[i] = b0[i];
    const int pbase = blockIdx.x * 64;
    for (int i = tid; i < 512; i += 256) ins[i] = hin[(size_t)pbase * 8 + i];
    __syncthreads();

    const int p     = tid & 63;
    const int chunk = tid >> 6;

    float in[8];
    #pragma unroll
    for (int k = 0; k < 8; ++k) in[k] = ins[p * 8 + k];

    __nv_bfloat16* Crow = C + ((size_t)(pbase + p)) * 512 + chunk * 128;
    const int cb = chunk * 128;

    #pragma unroll 2
    for (int j0 = 0; j0 < 128; j0 += 8) {
        float o[8];
        #pragma unroll
        for (int q = 0; q < 8; ++q) o[q] = b0s[cb + j0 + q];
        #pragma unroll
        for (int k = 0; k < 8; ++k) {
            float4 lo = *(const float4*)&w0s[k * 512 + cb + j0];
            float4 hi = *(const float4*)&w0s[k * 512 + cb + j0 + 4];
            o[0] += in[k] * lo.x; o[1] += in[k] * lo.y;
            o[2] += in[k] * lo.z; o[3] += in[k] * lo.w;
            o[4] += in[k] * hi.x; o[5] += in[k] * hi.y;
            o[6] += in[k] * hi.z; o[7] += in[k] * hi.w;
        }
        __nv_bfloat162 v[4];
        #pragma unroll
        for (int q = 0; q < 4; ++q)
            v[q] = __floats2bfloat162_rn(fmaxf(o[2*q], 0.0f), fmaxf(o[2*q+1], 0.0f));
        *(uint4*)(Crow + j0) = *(uint4*)v;
    }
}

// ---------------- bf16 tensor-core GEMM, K=512, ldmatrix fragments ---------
#define W_STRIDE 20
#define ROWB (W_STRIDE * 4)

__global__ __launch_bounds__(256, 2)
void bf16_gemm(const __nv_bfloat16* __restrict__ A,
               const __nv_bfloat16* __restrict__ Bt,
               const float* __restrict__ bias,
               __nv_bfloat16* __restrict__ C)
{
    __shared__ uint32_t As[2][128 * W_STRIDE];
    __shared__ uint32_t Bs[2][128 * W_STRIDE];

    const int tid  = threadIdx.x;
    const int bN   = blockIdx.x;
    const int bM   = blockIdx.y;
    const int lane = tid & 31;
    const int warp = tid >> 5;
    const int wM = warp >> 2;
    const int wN = warp & 3;
    const int g  = lane >> 2;
    const int tg = lane & 3;

    const int ldrow = tid >> 2;
    const int ldch  = tid & 3;

    uint32_t sA0 = (uint32_t)__cvta_generic_to_shared(&As[0][0]);
    uint32_t sA1 = (uint32_t)__cvta_generic_to_shared(&As[1][0]);
    uint32_t sB0 = (uint32_t)__cvta_generic_to_shared(&Bs[0][0]);
    uint32_t sB1 = (uint32_t)__cvta_generic_to_shared(&Bs[1][0]);

    const uint32_t offA = (uint32_t)((lane & 15) * ROWB + ((lane >> 4) * 16))
                        + (uint32_t)(wM * 64 * ROWB);
    const uint32_t offB = (uint32_t)(((lane & 7) + ((lane >> 4) << 3)) * ROWB
                        + (((lane >> 3) & 1) * 16))
                        + (uint32_t)(wN * 32 * ROWB);

    const __nv_bfloat16* Agb = A  + ((size_t)bM * 128 + ldrow) * 512 + ldch * 8;
    const __nv_bfloat16* Bgb = Bt + ((size_t)bN * 128 + ldrow) * 512 + ldch * 8;

    float acc[4][4][4];
    #pragma unroll
    for (int i = 0; i < 4; ++i)
        #pragma unroll
        for (int j = 0; j < 4; ++j)
            #pragma unroll
            for (int q = 0; q < 4; ++q) acc[i][j][q] = 0.0f;

    auto issue = [&](int kt, uint32_t sA, uint32_t sB) {
        const __nv_bfloat16* Ag = Agb + kt * 32;
        uint32_t da = sA + ((ldrow * W_STRIDE + ldch * 4) << 2);
        cpa16(da, Ag);
        cpa16(da + ((64 * W_STRIDE) << 2), Ag + (size_t)64 * 512);
        const __nv_bfloat16* Bg = Bgb + kt * 32;
        uint32_t db = sB + ((ldrow * W_STRIDE + ldch * 4) << 2);
        cpa16(db, Bg);
        cpa16(db + ((64 * W_STRIDE) << 2), Bg + (size_t)64 * 512);
    };

    issue(0, sA0, sB0);
    cpa_commit();

    #pragma unroll 1
    for (int t = 0; t < 16; ++t) {
        int cur = t & 1;
        if (t < 15) {
            issue(t + 1, cur ? sA0 : sA1, cur ? sB0 : sB1);
            cpa_commit();
            cpa_wait<1>();
        } else {
            cpa_wait<0>();
        }
        __syncthreads();

        uint32_t aBase = (cur ? sA1 : sA0) + offA;
        uint32_t bBase = (cur ? sB1 : sB0) + offB;

        #pragma unroll
        for (int ks = 0; ks < 2; ++ks) {
            uint32_t a[4][4], bp[2][4];
            #pragma unroll
            for (int mf = 0; mf < 4; ++mf)
                ldm_x4(a[mf], aBase + mf * (16 * ROWB) + ks * 32);
            #pragma unroll
            for (int p = 0; p < 2; ++p)
                ldm_x4(bp[p], bBase + p * (16 * ROWB) + ks * 32);
            #pragma unroll
            for (int mf = 0; mf < 4; ++mf)
                #pragma unroll
                for (int nf = 0; nf < 4; ++nf)
                    mma_bf16(acc[mf][nf], a[mf], &bp[nf >> 1][(nf & 1) * 2]);
        }
        __syncthreads();
    }

    #pragma unroll
    for (int mf = 0; mf < 4; ++mf) {
        int row0 = bM * 128 + wM * 64 + mf * 16 + g;
        #pragma unroll
        for (int nf = 0; nf < 4; ++nf) {
            int col = bN * 128 + wN * 32 + nf * 8 + tg * 2;
            float b0 = bias[col], b1 = bias[col + 1];
            float v00 = fmaxf(acc[mf][nf][0] + b0, 0.0f);
            float v01 = fmaxf(acc[mf][nf][1] + b1, 0.0f);
            float v10 = fmaxf(acc[mf][nf][2] + b0, 0.0f);
            float v11 = fmaxf(acc[mf][nf][3] + b1, 0.0f);
            *(__nv_bfloat162*)(C + (size_t)row0 * 512 + col) =
                __floats2bfloat162_rn(v00, v01);
            *(__nv_bfloat162*)(C + (size_t)(row0 + 8) * 512 + col) =
                __floats2bfloat162_rn(v10, v11);
        }
    }
}

// ---------------- head: [N,512] @ wct^T(32x512) -> fp32 cs[N][32] ----------
__global__ __launch_bounds__(256, 2)
void head_gemm(const __nv_bfloat16* __restrict__ A,
               const __nv_bfloat16* __restrict__ Bt,   // [32][512]
               const float* __restrict__ bias,          // [32]
               float* __restrict__ cs)                  // [N][32]
{
    __shared__ uint32_t As[2][128 * W_STRIDE];
    __shared__ uint32_t Bs[2][32 * W_STRIDE];

    const int tid  = threadIdx.x;
    const int bM   = blockIdx.y;
    const int lane = tid & 31;
    const int warp = tid >> 5;       // 0..7, each owns 16 rows x 32 cols
    const int g  = lane >> 2;
    const int tg = lane & 3;

    const int ldrow = tid >> 2;
    const int ldch  = tid & 3;

    uint32_t sA0 = (uint32_t)__cvta_generic_to_shared(&As[0][0]);
    uint32_t sA1 = (uint32_t)__cvta_generic_to_shared(&As[1][0]);
    uint32_t sB0 = (uint32_t)__cvta_generic_to_shared(&Bs[0][0]);
    uint32_t sB1 = (uint32_t)__cvta_generic_to_shared(&Bs[1][0]);

    const uint32_t offA = (uint32_t)((lane & 15) * ROWB + ((lane >> 4) * 16))
                        + (uint32_t)(warp * 16 * ROWB);
    const uint32_t offB = (uint32_t)(((lane & 7) + ((lane >> 4) << 3)) * ROWB
                        + (((lane >> 3) & 1) * 16));

    const __nv_bfloat16* Agb = A  + ((size_t)bM * 128 + ldrow) * 512 + ldch * 8;
    const __nv_bfloat16* Bgb = Bt + ((size_t)(ldrow & 31)) * 512 + ldch * 8;

    float acc[4][4];
    #pragma unroll
    for (int j = 0; j < 4; ++j)
        #pragma unroll
        for (int q = 0; q < 4; ++q) acc[j][q] = 0.0f;

    auto issue = [&](int kt, uint32_t sA, uint32_t sB) {
        const __nv_bfloat16* Ag = Agb + kt * 32;
        uint32_t da = sA + ((ldrow * W_STRIDE + ldch * 4) << 2);
        cpa16(da, Ag);
        cpa16(da + ((64 * W_STRIDE) << 2), Ag + (size_t)64 * 512);
        if (tid < 128) {
            const __nv_bfloat16* Bg = Bgb + kt * 32;
            uint32_t db = sB + ((ldrow * W_STRIDE + ldch * 4) << 2);
            cpa16(db, Bg);
        }
    };

    issue(0, sA0, sB0);
    cpa_commit();

    #pragma unroll 1
    for (int t = 0; t < 16; ++t) {
        int cur = t & 1;
        if (t < 15) {
            issue(t + 1, cur ? sA0 : sA1, cur ? sB0 : sB1);
            cpa_commit();
            cpa_wait<1>();
        } else {
            cpa_wait<0>();
        }
        __syncthreads();

        uint32_t aBase = (cur ? sA1 : sA0) + offA;
        uint32_t bBase = (cur ? sB1 : sB0) + offB;

        #pragma unroll
        for (int ks = 0; ks < 2; ++ks) {
            uint32_t a[4], bp[2][4];
            ldm_x4(a, aBase + ks * 32);
            #pragma unroll
            for (int p = 0; p < 2; ++p)
                ldm_x4(bp[p], bBase + p * (16 * ROWB) + ks * 32);
            #pragma unroll
            for (int nf = 0; nf < 4; ++nf)
                mma_bf16(acc[nf], a, &bp[nf >> 1][(nf & 1) * 2]);
        }
        __syncthreads();
    }

    const int row0 = bM * 128 + warp * 16 + g;
    #pragma unroll
    for (int nf = 0; nf < 4; ++nf) {
        int col = nf * 8 + tg * 2;
        float b0 = bias[col], b1 = bias[col + 1];
        *(float2*)(cs + (size_t)row0 * 32 + col) =
            make_float2(acc[nf][0] + b0, acc[nf][1] + b1);
        *(float2*)(cs + (size_t)(row0 + 8) * 32 + col) =
            make_float2(acc[nf][2] + b0, acc[nf][3] + b1);
    }
}

// ---------------- weight transpose + bf16 convert ----------------
__global__ void wt_kernel(const float* __restrict__ w1,
                          const float* __restrict__ w2,
                          const float* __restrict__ w3,
                          __nv_bfloat16* __restrict__ o1,
                          __nv_bfloat16* __restrict__ o2,
                          __nv_bfloat16* __restrict__ o3)
{
    __shared__ float tile[32][33];
    const float* src = (blockIdx.z == 0) ? w1 : (blockIdx.z == 1) ? w2 : w3;
    __nv_bfloat16* dst = (blockIdx.z == 0) ? o1 : (blockIdx.z == 1) ? o2 : o3;

    int bx = blockIdx.x * 32;
    int by = blockIdx.y * 32;
    int tx = threadIdx.x, ty = threadIdx.y;

    #pragma unroll
    for (int j = 0; j < 32; j += 8)
        tile[ty + j][tx] = src[(size_t)(bx + ty + j) * 512 + by + tx];
    __syncthreads();
    #pragma unroll
    for (int j = 0; j < 32; j += 8)
        dst[(size_t)(by + ty + j) * 512 + bx + tx] =
            __float2bfloat16_rn(tile[tx][ty + j]);
}

// ---------------- head weight prep: wc[512][27] -> wct[32][512] bf16 -------
__global__ void headprep_kernel(const float* __restrict__ wc,
                                const float* __restrict__ bc,
                                __nv_bfloat16* __restrict__ wct,
                                float* __restrict__ bcp)
{
    int i = blockIdx.x * blockDim.x + threadIdx.x;
    if (i < 32 * 512) {
        int n = i / 512, k = i % 512;
        wct[i] = __float2bfloat16_rn((n < 27) ? wc[(size_t)k * 27 + n] : 0.0f);
    }
    if (i < 32) bcp[i] = (i < 27) ? bc[i] : 0.0f;
}

// ---------------- kernel C: gate + specular + raw_rgb ----------------
__global__ void final_kernel(const float* __restrict__ feature,
                             const float* __restrict__ cs,   // [N][32]
                             float* __restrict__ out,
                             int N)
{
    int n = blockIdx.x * blockDim.x + threadIdx.x;
    if (n >= N) return;

    const float* f = feature + (size_t)n * 16;
    const float* c = cs + (size_t)n * 32;

    float g0 = 0.f, g1 = 0.f, g2 = 0.f;
    #pragma unroll
    for (int j = 0; j < 9; ++j) {
        float coe = f[1 + j];
        g0 += c[j]      * coe;
        g1 += c[9 + j]  * coe;
        g2 += c[18 + j] * coe;
    }
    g0 = sigmoidf_(g0); g1 = sigmoidf_(g1); g2 = sigmoidf_(g2);

    float sp0 = sigmoidf_(f[13]);
    float sp1 = sigmoidf_(f[14]);
    float sp2 = sigmoidf_(f[15]);

    size_t N3 = 3 * (size_t)N;
    size_t p3 = (size_t)n * 3;

    float li0 = out[4*N3 + p3 + 0];
    float li1 = out[4*N3 + p3 + 1];
    float li2 = out[4*N3 + p3 + 2];

    float s0 = sp0 * li0 * g0;
    float s1 = sp1 * li1 * g1;
    float s2 = sp2 * li2 * g2;

    out[3*N3 + p3 + 0] = s0;
    out[3*N3 + p3 + 1] = s1;
    out[3*N3 + p3 + 2] = s2;
    out[p3 + 0] = out[2*N3 + p3 + 0] + s0;
    out[p3 + 1] = out[2*N3 + p3 + 1] + s1;
    out[p3 + 2] = out[2*N3 + p3 + 2] + s2;
}

// ---------------- launch ----------------
extern "C" void kernel_launch(void* const* d_in, const int* in_sizes, int n_in,
                              void* d_out, int out_size)
{
    const float* normals   = (const float*)d_in[0];
    const float* view_dirs = (const float*)d_in[1];
    const float* feature   = (const float*)d_in[2];
    const float* ref_SH    = (const float*)d_in[3];
    const float* w0 = (const float*)d_in[4];
    const float* b0 = (const float*)d_in[5];
    const float* w1 = (const float*)d_in[6];
    const float* b1 = (const float*)d_in[7];
    const float* w2 = (const float*)d_in[8];
    const float* b2 = (const float*)d_in[9];
    const float* w3 = (const float*)d_in[10];
    const float* b3 = (const float*)d_in[11];
    const float* wc = (const float*)d_in[12];
    const float* bc = (const float*)d_in[13];

    int N = in_sizes[0] / 3;
    float* out = (float*)d_out;

    float *hin, *cs, *bcp;
    __nv_bfloat16 *hb0, *hb1, *w1b, *w2b, *w3b, *wct;
    cudaGetSymbolAddress((void**)&hin, g_hin);
    cudaGetSymbolAddress((void**)&hb0, g_hb0);
    cudaGetSymbolAddress((void**)&hb1, g_hb1);
    cudaGetSymbolAddress((void**)&cs,  g_cs);
    cudaGetSymbolAddress((void**)&w1b, g_w1b);
    cudaGetSymbolAddress((void**)&w2b, g_w2b);
    cudaGetSymbolAddress((void**)&w3b, g_w3b);
    cudaGetSymbolAddress((void**)&wct, g_wct);
    cudaGetSymbolAddress((void**)&bcp, g_bcp);

    point_kernel<<<(N + 127) / 128, 128>>>(normals, view_dirs, feature, ref_SH,
                                           out, hin, N);
    wt_kernel<<<dim3(16, 16, 3), dim3(32, 8)>>>(w1, w2, w3, w1b, w2b, w3b);
    headprep_kernel<<<(32 * 512 + 255) / 256, 256>>>(wc, bc, wct, bcp);

    int mtiles = N / 128;
    layer0_kernel<<<N / 64, 256>>>(hin, w0, b0, hb0);
    bf16_gemm<<<dim3(4, mtiles), 256>>>(hb0, w1b, b1, hb1);
    bf16_gemm<<<dim3(4, mtiles), 256>>>(hb1, w2b, b2, hb0);
    bf16_gemm<<<dim3(4, mtiles), 256>>>(hb0, w3b, b3, hb1);
    head_gemm<<<dim3(1, mtiles), 256>>>(hb1, wct, bcp, cs);

    final_kernel<<<(N + 255) / 256, 256>>>(feature, cs, out, N);
}